// round 7
// baseline (speedup 1.0000x reference)
#include <cuda_runtime.h>
#include <math.h>
#include <stdint.h>

#define T_TOK 100352   // 32*56*56 tokens
#define DIM   128
#define INNER 512
#define QKV3  1536
#define MLPD  512
#define HEADS 4
#define DISP  3
#define NEGM  (-1e9f)

// ---------------- scratch (static device globals; no allocations) ----------------
__device__ float g_h  [T_TOK * DIM];
__device__ float g_xn [T_TOK * DIM];
__device__ float g_qkv[T_TOK * QKV3];
__device__ float g_mid[T_TOK * INNER];

// ---------------- patch embed + fused LN ----------------
__global__ void patch_embed_ln_kernel(const float* __restrict__ x,
                                      const float* __restrict__ w,
                                      const float* __restrict__ b,
                                      const float* __restrict__ ga,
                                      const float* __restrict__ be,
                                      float* __restrict__ out_h,
                                      float* __restrict__ out_xn)
{
    int t = blockIdx.x, n = threadIdx.x;
    __shared__ float s[48];
    __shared__ float red[4];
    int bb = t / 3136, rem = t % 3136, ph = rem / 56, pw = rem % 56;
    if (n < 48) {
        int c = n >> 4, pi = (n >> 2) & 3, pj = n & 3;
        s[n] = x[((size_t)(bb * 3 + c) * 224 + (ph * 4 + pi)) * 224 + (pw * 4 + pj)];
    }
    __syncthreads();
    float acc = b[n];
    #pragma unroll
    for (int f = 0; f < 48; f++) acc += s[f] * w[f * DIM + n];
    out_h[(size_t)t * DIM + n] = acc;

    // LN over the 128 channels of this token
    float v = acc, sum = v;
    #pragma unroll
    for (int o = 16; o; o >>= 1) sum += __shfl_xor_sync(~0u, sum, o);
    if ((n & 31) == 0) red[n >> 5] = sum;
    __syncthreads();
    float mean = (red[0] + red[1] + red[2] + red[3]) * (1.f / 128.f);
    __syncthreads();
    float d = v - mean;
    sum = d * d;
    #pragma unroll
    for (int o = 16; o; o >>= 1) sum += __shfl_xor_sync(~0u, sum, o);
    if ((n & 31) == 0) red[n >> 5] = sum;
    __syncthreads();
    float var = (red[0] + red[1] + red[2] + red[3]) * (1.f / 128.f);
    out_xn[(size_t)t * DIM + n] = d * rsqrtf(var + 1e-5f) * ga[n] + be[n];
}

// ---------------- TF32 tensor-core GEMM 128x128xBK16, 8 warps ----------------
__device__ __forceinline__ float gelu_f(float v)
{
    return 0.5f * v * (1.f + erff(v * 0.70710678118654752f));
}

__device__ __forceinline__ float tf32r(float x)
{
    uint32_t u;
    asm("cvt.rna.tf32.f32 %0, %1;" : "=r"(u) : "f"(x));
    return __uint_as_float(u);
}

__device__ __forceinline__ void mma_tf32(float c[4], const uint32_t a[4], const uint32_t b[2])
{
    asm volatile(
        "mma.sync.aligned.m16n8k8.row.col.f32.tf32.tf32.f32 "
        "{%0,%1,%2,%3}, {%4,%5,%6,%7}, {%8,%9}, {%0,%1,%2,%3};"
        : "+f"(c[0]), "+f"(c[1]), "+f"(c[2]), "+f"(c[3])
        : "r"(a[0]), "r"(a[1]), "r"(a[2]), "r"(a[3]), "r"(b[0]), "r"(b[1]));
}

// OP: 0 = +bias, 1 = +bias+residual, 2 = +bias+GELU,
//     3 = +bias+residual, write C, and write C2 = LayerNorm(C)*ga+be  (requires N==128, grid.x==1)
template <int OP, int K, int N>
__global__ void __launch_bounds__(256)
tgemm_kernel(const float* __restrict__ A, const float* __restrict__ B,
             const float* __restrict__ bias, const float* __restrict__ R,
             float* __restrict__ C,
             const float* __restrict__ ga, const float* __restrict__ be,
             float* __restrict__ C2)
{
    __shared__ float As[2][16][136];
    __shared__ float Bs[2][16][136];
    __shared__ float2 rstat[128][4];   // fused-LN row partials (sum, sumsq)

    int tid  = threadIdx.x;
    int lane = tid & 31, wid = tid >> 5;
    int g = lane >> 2, tig = lane & 3;
    int warp_m = (wid & 1) * 64, warp_n = (wid >> 1) * 32;
    int row0 = blockIdx.y * 128, col0 = blockIdx.x * 128;

    int am = tid & 127, ak = (tid >> 7) * 8;
    int bn = (tid & 31) * 4, bk = tid >> 5;

    float acc[4][4][4];
    #pragma unroll
    for (int mt = 0; mt < 4; mt++)
        #pragma unroll
        for (int nt = 0; nt < 4; nt++)
            #pragma unroll
            for (int r = 0; r < 4; r++) acc[mt][nt][r] = 0.f;

    const float* Aptr = A + (size_t)(row0 + am) * K + ak;
    const float* Bptr = B + (size_t)bk * N + col0 + bn;

    float4 a0 = *(const float4*)(Aptr);
    float4 a1 = *(const float4*)(Aptr + 4);
    float4 b0 = *(const float4*)(Bptr);
    float4 b1 = *(const float4*)(Bptr + (size_t)8 * N);

    As[0][ak + 0][am] = tf32r(a0.x); As[0][ak + 1][am] = tf32r(a0.y);
    As[0][ak + 2][am] = tf32r(a0.z); As[0][ak + 3][am] = tf32r(a0.w);
    As[0][ak + 4][am] = tf32r(a1.x); As[0][ak + 5][am] = tf32r(a1.y);
    As[0][ak + 6][am] = tf32r(a1.z); As[0][ak + 7][am] = tf32r(a1.w);
    {
        float4 c0 = make_float4(tf32r(b0.x), tf32r(b0.y), tf32r(b0.z), tf32r(b0.w));
        float4 c1 = make_float4(tf32r(b1.x), tf32r(b1.y), tf32r(b1.z), tf32r(b1.w));
        *(float4*)&Bs[0][bk][bn] = c0;
        *(float4*)&Bs[0][bk + 8][bn] = c1;
    }
    __syncthreads();

    int buf = 0;
    #pragma unroll 2
    for (int k0 = 0; k0 < K; k0 += 16) {
        const bool more = (k0 + 16) < K;
        if (more) {
            a0 = *(const float4*)(Aptr + k0 + 16);
            a1 = *(const float4*)(Aptr + k0 + 20);
            b0 = *(const float4*)(Bptr + (size_t)(k0 + 16) * N);
            b1 = *(const float4*)(Bptr + (size_t)(k0 + 24) * N);
        }
        #pragma unroll
        for (int ks = 0; ks < 2; ks++) {
            int kb = ks * 8;
            uint32_t af[4][4], bfr[4][2];
            #pragma unroll
            for (int mt = 0; mt < 4; mt++) {
                int m0 = warp_m + mt * 16;
                af[mt][0] = __float_as_uint(As[buf][kb + tig    ][m0 + g    ]);
                af[mt][1] = __float_as_uint(As[buf][kb + tig    ][m0 + g + 8]);
                af[mt][2] = __float_as_uint(As[buf][kb + tig + 4][m0 + g    ]);
                af[mt][3] = __float_as_uint(As[buf][kb + tig + 4][m0 + g + 8]);
            }
            #pragma unroll
            for (int nt = 0; nt < 4; nt++) {
                int n0 = warp_n + nt * 8;
                bfr[nt][0] = __float_as_uint(Bs[buf][kb + tig    ][n0 + g]);
                bfr[nt][1] = __float_as_uint(Bs[buf][kb + tig + 4][n0 + g]);
            }
            #pragma unroll
            for (int mt = 0; mt < 4; mt++)
                #pragma unroll
                for (int nt = 0; nt < 4; nt++)
                    mma_tf32(acc[mt][nt], af[mt], bfr[nt]);
        }
        if (more) {
            int nb = buf ^ 1;
            As[nb][ak + 0][am] = tf32r(a0.x); As[nb][ak + 1][am] = tf32r(a0.y);
            As[nb][ak + 2][am] = tf32r(a0.z); As[nb][ak + 3][am] = tf32r(a0.w);
            As[nb][ak + 4][am] = tf32r(a1.x); As[nb][ak + 5][am] = tf32r(a1.y);
            As[nb][ak + 6][am] = tf32r(a1.z); As[nb][ak + 7][am] = tf32r(a1.w);
            float4 c0 = make_float4(tf32r(b0.x), tf32r(b0.y), tf32r(b0.z), tf32r(b0.w));
            float4 c1 = make_float4(tf32r(b1.x), tf32r(b1.y), tf32r(b1.z), tf32r(b1.w));
            *(float4*)&Bs[nb][bk][bn] = c0;
            *(float4*)&Bs[nb][bk + 8][bn] = c1;
            __syncthreads();
            buf = nb;
        }
    }

    // ---- epilogue: fold bias (+residual), apply GELU, store C ----
    #pragma unroll
    for (int mt = 0; mt < 4; mt++) {
        #pragma unroll
        for (int nt = 0; nt < 4; nt++) {
            int r = row0 + warp_m + mt * 16 + g;
            int c = col0 + warp_n + nt * 8 + 2 * tig;
            if (bias) {
                float2 bb = *(const float2*)&bias[c];
                acc[mt][nt][0] += bb.x; acc[mt][nt][1] += bb.y;
                acc[mt][nt][2] += bb.x; acc[mt][nt][3] += bb.y;
            }
            if (OP == 1 || OP == 3) {
                float2 r0 = *(const float2*)&R[(size_t)r * N + c];
                float2 r1 = *(const float2*)&R[(size_t)(r + 8) * N + c];
                acc[mt][nt][0] += r0.x; acc[mt][nt][1] += r0.y;
                acc[mt][nt][2] += r1.x; acc[mt][nt][3] += r1.y;
            }
            if (OP == 2) {
                acc[mt][nt][0] = gelu_f(acc[mt][nt][0]);
                acc[mt][nt][1] = gelu_f(acc[mt][nt][1]);
                acc[mt][nt][2] = gelu_f(acc[mt][nt][2]);
                acc[mt][nt][3] = gelu_f(acc[mt][nt][3]);
            }
            float2 o0 = make_float2(acc[mt][nt][0], acc[mt][nt][1]);
            float2 o1 = make_float2(acc[mt][nt][2], acc[mt][nt][3]);
            *(float2*)&C[(size_t)r * N + c] = o0;
            *(float2*)&C[(size_t)(r + 8) * N + c] = o1;
        }
    }

    // ---- fused LayerNorm (OP==3, N==128, full rows in this CTA) ----
    if (OP == 3) {
        #pragma unroll
        for (int mt = 0; mt < 4; mt++) {
            #pragma unroll
            for (int hh = 0; hh < 2; hh++) {
                float s = 0.f, q = 0.f;
                #pragma unroll
                for (int nt = 0; nt < 4; nt++) {
                    float a0 = acc[mt][nt][hh * 2], a1 = acc[mt][nt][hh * 2 + 1];
                    s += a0 + a1; q += a0 * a0 + a1 * a1;
                }
                s += __shfl_xor_sync(~0u, s, 1); q += __shfl_xor_sync(~0u, q, 1);
                s += __shfl_xor_sync(~0u, s, 2); q += __shfl_xor_sync(~0u, q, 2);
                if (tig == 0) {
                    int row = warp_m + mt * 16 + g + hh * 8;
                    rstat[row][wid >> 1] = make_float2(s, q);
                }
            }
        }
        __syncthreads();
        #pragma unroll
        for (int mt = 0; mt < 4; mt++) {
            float mean[2], inv[2];
            #pragma unroll
            for (int hh = 0; hh < 2; hh++) {
                int rowl = warp_m + mt * 16 + g + hh * 8;
                float2 t0 = rstat[rowl][0], t1 = rstat[rowl][1];
                float2 t2 = rstat[rowl][2], t3 = rstat[rowl][3];
                float s = t0.x + t1.x + t2.x + t3.x;
                float q = t0.y + t1.y + t2.y + t3.y;
                mean[hh] = s * (1.f / 128.f);
                float var = q * (1.f / 128.f) - mean[hh] * mean[hh];
                inv[hh] = rsqrtf(var + 1e-5f);
            }
            #pragma unroll
            for (int nt = 0; nt < 4; nt++) {
                int r = row0 + warp_m + mt * 16 + g;
                int c = warp_n + nt * 8 + 2 * tig;
                float2 gg = *(const float2*)&ga[c];
                float2 bb = *(const float2*)&be[c];
                float2 o0 = make_float2(
                    (acc[mt][nt][0] - mean[0]) * inv[0] * gg.x + bb.x,
                    (acc[mt][nt][1] - mean[0]) * inv[0] * gg.y + bb.y);
                float2 o1 = make_float2(
                    (acc[mt][nt][2] - mean[1]) * inv[1] * gg.x + bb.x,
                    (acc[mt][nt][3] - mean[1]) * inv[1] * gg.y + bb.y);
                *(float2*)&C2[(size_t)r * 128 + c] = o0;
                *(float2*)&C2[(size_t)(r + 8) * 128 + c] = o1;
            }
        }
    }
}

// ---------------- fused window attention (QK 4-row tiles, V in registers) ----------------
// grid: (64 windows, 4 heads, 32 batch); 128 threads.
__global__ void attn_kernel(const float* __restrict__ qkv,
                            const float* __restrict__ pos,
                            float* __restrict__ out, int shift)
{
    __shared__ float KT[49 * 128];     // K transposed [d][j]
    __shared__ float S[49 * 52];       // softmax probs, padded rows
    __shared__ float Qs[4][4][128];    // 4 q rows per warp
    __shared__ float poss[169];

    int tid = threadIdx.x;
    int win = blockIdx.x, head = blockIdx.y, bb = blockIdx.z;
    int win_i = win >> 3, win_j = win & 7;

    for (int idx = tid; idx < 169; idx += 128) poss[idx] = pos[idx];

    int d = tid;
    float vreg[49];
    #pragma unroll
    for (int j = 0; j < 49; j++) {
        int wi = j / 7, wj = j % 7;
        int ui = (win_i * 7 + wi + shift) % 56;
        int uj = (win_j * 7 + wj + shift) % 56;
        size_t base = (size_t)(bb * 3136 + ui * 56 + uj) * 1536 + head * 128 + d;
        KT[d * 49 + j] = qkv[base + 512];
        vreg[j]        = qkv[base + 1024];
    }
    __syncthreads();

    int w = tid >> 5, l = tid & 31;
    int j1 = (l < 17) ? (l + 32) : 0;
    const float scale = 0.08838834764831845f;  // 128^-0.5

    for (int i0 = w * 4; i0 < 49; i0 += 16) {
        __syncwarp();
        #pragma unroll
        for (int r = 0; r < 4; r++) {
            int ir = i0 + r;
            if (ir < 49) {
                int wi = ir / 7, wj = ir % 7;
                int ui = (win_i * 7 + wi + shift) % 56;
                int uj = (win_j * 7 + wj + shift) % 56;
                const float* qp =
                    &qkv[(size_t)(bb * 3136 + ui * 56 + uj) * 1536 + head * 128];
                Qs[w][r][l]      = qp[l];      Qs[w][r][l + 32] = qp[l + 32];
                Qs[w][r][l + 64] = qp[l + 64]; Qs[w][r][l + 96] = qp[l + 96];
            }
        }
        __syncwarp();

        float s0[4] = {0.f, 0.f, 0.f, 0.f}, s1[4] = {0.f, 0.f, 0.f, 0.f};
        #pragma unroll 4
        for (int dd = 0; dd < 128; dd++) {
            float k0 = KT[dd * 49 + l];
            float k1 = KT[dd * 49 + j1];
            #pragma unroll
            for (int r = 0; r < 4; r++) {
                float qv = Qs[w][r][dd];
                s0[r] += qv * k0;
                s1[r] += qv * k1;
            }
        }

        #pragma unroll
        for (int r = 0; r < 4; r++) {
            int i = i0 + r;
            if (i >= 49) break;   // warp-uniform
            int wi = i / 7, wj = i % 7;
            int jj0 = l, jj1 = l + 32;
            float v0 = s0[r] * scale + poss[(jj0 / 7 - wi + 6) * 13 + (jj0 % 7 - wj + 6)];
            float v1 = (l < 17)
                ? s1[r] * scale + poss[(jj1 / 7 - wi + 6) * 13 + (jj1 % 7 - wj + 6)]
                : -3.0e38f;
            if (shift) {
                if (win_i == 7) {
                    if ((i >= 28) != (jj0 >= 28)) v0 += NEGM;
                    if (l < 17 && ((i >= 28) != (jj1 >= 28))) v1 += NEGM;
                }
                if (win_j == 7) {
                    if ((wj >= 4) != (jj0 % 7 >= 4)) v0 += NEGM;
                    if (l < 17 && ((wj >= 4) != (jj1 % 7 >= 4))) v1 += NEGM;
                }
            }
            float m = v0; if (l < 17) m = fmaxf(m, v1);
            #pragma unroll
            for (int o = 16; o; o >>= 1) m = fmaxf(m, __shfl_xor_sync(~0u, m, o));
            float e0 = expf(v0 - m);
            float e1 = (l < 17) ? expf(v1 - m) : 0.f;
            float sm = e0 + e1;
            #pragma unroll
            for (int o = 16; o; o >>= 1) sm += __shfl_xor_sync(~0u, sm, o);
            float inv = 1.f / sm;
            S[i * 52 + jj0] = e0 * inv;
            if (l < 17) S[i * 52 + jj1] = e1 * inv;
        }
    }
    __syncthreads();

    // AV: out[i][d] = sum_j S[i][j] * vreg[j]; S rows as warp-broadcast float4
    #pragma unroll 1
    for (int i = 0; i < 49; i++) {
        const float* srow = &S[i * 52];
        float acc = 0.f;
        #pragma unroll
        for (int jq = 0; jq < 12; jq++) {
            float4 s4 = *(const float4*)(srow + jq * 4);
            acc += s4.x * vreg[jq * 4 + 0] + s4.y * vreg[jq * 4 + 1]
                 + s4.z * vreg[jq * 4 + 2] + s4.w * vreg[jq * 4 + 3];
        }
        acc += srow[48] * vreg[48];
        int wi = i / 7, wj = i % 7;
        int ui = (win_i * 7 + wi + shift) % 56;
        int uj = (win_j * 7 + wj + shift) % 56;
        out[(size_t)(bb * 3136 + ui * 56 + uj) * 512 + head * 128 + d] = acc;
    }
}

// ---------------- host launcher ----------------
extern "C" void kernel_launch(void* const* d_in, const int* in_sizes, int n_in,
                              void* d_out, int out_size)
{
    const float* x    = (const float*)d_in[0];
    const float* w_pe = (const float*)d_in[1];
    const float* b_pe = (const float*)d_in[2];

    float *h, *xn, *qkv, *mid;
    cudaGetSymbolAddress((void**)&h,   g_h);
    cudaGetSymbolAddress((void**)&xn,  g_xn);
    cudaGetSymbolAddress((void**)&qkv, g_qkv);
    cudaGetSymbolAddress((void**)&mid, g_mid);
    float* out = (float*)d_out;

    const float* const* pa = (const float* const*)(d_in + 3);
    const float* const* pb = (const float* const*)(d_in + 15);

    // patch embed + ln1_a fused
    patch_embed_ln_kernel<<<T_TOK, 128>>>(x, w_pe, b_pe, pa[0], pa[1], h, xn);

    for (int blk = 0; blk < 2; blk++) {
        const float* const* p = blk ? pb : pa;
        const float *wqkv = p[2], *pos = p[3], *wo = p[4], *bo = p[5],
                    *ga2 = p[6], *be2 = p[7], *w1 = p[8], *b1 = p[9],
                    *w2 = p[10], *b2 = p[11];
        int shift = blk ? DISP : 0;

        tgemm_kernel<0, DIM, QKV3><<<dim3(QKV3 / 128, T_TOK / 128), 256>>>(
            xn, wqkv, nullptr, nullptr, qkv, nullptr, nullptr, nullptr);
        attn_kernel<<<dim3(64, HEADS, 32), 128>>>(qkv, pos, mid, shift);
        // w_o + residual, fused ln2 -> xn
        tgemm_kernel<3, INNER, DIM><<<dim3(1, T_TOK / 128), 256>>>(
            mid, wo, bo, h, h, ga2, be2, xn);
        tgemm_kernel<2, DIM, MLPD><<<dim3(MLPD / 128, T_TOK / 128), 256>>>(
            xn, w1, b1, nullptr, mid, nullptr, nullptr, nullptr);
        if (blk == 0) {
            // mlp2 + residual -> h, fused ln1_b -> xn
            tgemm_kernel<3, MLPD, DIM><<<dim3(1, T_TOK / 128), 256>>>(
                mid, w2, b2, h, h, pb[0], pb[1], xn);
        } else {
            tgemm_kernel<1, MLPD, DIM><<<dim3(1, T_TOK / 128), 256>>>(
                mid, w2, b2, h, out, nullptr, nullptr, nullptr);
        }
    }
}

// round 8
// speedup vs baseline: 1.4622x; 1.4622x over previous
#include <cuda_runtime.h>
#include <math.h>
#include <stdint.h>

#define T_TOK 100352   // 32*56*56 tokens
#define DIM   128
#define INNER 512
#define QKV3  1536
#define MLPD  512
#define HEADS 4
#define DISP  3
#define NEGM  (-1e9f)

// ---------------- scratch (static device globals; no allocations) ----------------
__device__ float g_h  [T_TOK * DIM];
__device__ float g_xn [T_TOK * DIM];
__device__ float g_qkv[T_TOK * QKV3];
__device__ float g_mid[T_TOK * INNER];

// ---------------- patch embed + fused LN (ln1_a) ----------------
__global__ void patch_embed_ln_kernel(const float* __restrict__ x,
                                      const float* __restrict__ w,
                                      const float* __restrict__ b,
                                      const float* __restrict__ ga,
                                      const float* __restrict__ be,
                                      float* __restrict__ out_h,
                                      float* __restrict__ out_xn)
{
    int t = blockIdx.x, n = threadIdx.x;
    __shared__ float s[48];
    __shared__ float red[4];
    int bb = t / 3136, rem = t % 3136, ph = rem / 56, pw = rem % 56;
    if (n < 48) {
        int c = n >> 4, pi = (n >> 2) & 3, pj = n & 3;
        s[n] = x[((size_t)(bb * 3 + c) * 224 + (ph * 4 + pi)) * 224 + (pw * 4 + pj)];
    }
    __syncthreads();
    float acc = b[n];
    #pragma unroll
    for (int f = 0; f < 48; f++) acc += s[f] * w[f * DIM + n];
    out_h[(size_t)t * DIM + n] = acc;

    float v = acc, sum = v;
    #pragma unroll
    for (int o = 16; o; o >>= 1) sum += __shfl_xor_sync(~0u, sum, o);
    if ((n & 31) == 0) red[n >> 5] = sum;
    __syncthreads();
    float mean = (red[0] + red[1] + red[2] + red[3]) * (1.f / 128.f);
    __syncthreads();
    float d = v - mean;
    sum = d * d;
    #pragma unroll
    for (int o = 16; o; o >>= 1) sum += __shfl_xor_sync(~0u, sum, o);
    if ((n & 31) == 0) red[n >> 5] = sum;
    __syncthreads();
    float var = (red[0] + red[1] + red[2] + red[3]) * (1.f / 128.f);
    out_xn[(size_t)t * DIM + n] = d * rsqrtf(var + 1e-5f) * ga[n] + be[n];
}

// ---------------- LayerNorm (standalone) ----------------
__global__ void ln_kernel(const float* __restrict__ x,
                          const float* __restrict__ g,
                          const float* __restrict__ b,
                          float* __restrict__ y)
{
    int t = blockIdx.x, c = threadIdx.x;
    float v = x[(size_t)t * DIM + c];
    __shared__ float red[4];
    float s = v;
    #pragma unroll
    for (int o = 16; o; o >>= 1) s += __shfl_xor_sync(~0u, s, o);
    if ((c & 31) == 0) red[c >> 5] = s;
    __syncthreads();
    float mean = (red[0] + red[1] + red[2] + red[3]) * (1.f / 128.f);
    __syncthreads();
    float d = v - mean;
    s = d * d;
    #pragma unroll
    for (int o = 16; o; o >>= 1) s += __shfl_xor_sync(~0u, s, o);
    if ((c & 31) == 0) red[c >> 5] = s;
    __syncthreads();
    float var = (red[0] + red[1] + red[2] + red[3]) * (1.f / 128.f);
    y[(size_t)t * DIM + c] = d * rsqrtf(var + 1e-5f) * g[c] + b[c];
}

// ---------------- TF32 tensor-core GEMM 128x128xBK16, 8 warps (lean, R5 form) ----------------
__device__ __forceinline__ float gelu_f(float v)
{
    return 0.5f * v * (1.f + erff(v * 0.70710678118654752f));
}

__device__ __forceinline__ float tf32r(float x)
{
    uint32_t u;
    asm("cvt.rna.tf32.f32 %0, %1;" : "=r"(u) : "f"(x));
    return __uint_as_float(u);
}

__device__ __forceinline__ void mma_tf32(float c[4], const uint32_t a[4], const uint32_t b[2])
{
    asm volatile(
        "mma.sync.aligned.m16n8k8.row.col.f32.tf32.tf32.f32 "
        "{%0,%1,%2,%3}, {%4,%5,%6,%7}, {%8,%9}, {%0,%1,%2,%3};"
        : "+f"(c[0]), "+f"(c[1]), "+f"(c[2]), "+f"(c[3])
        : "r"(a[0]), "r"(a[1]), "r"(a[2]), "r"(a[3]), "r"(b[0]), "r"(b[1]));
}

// OP: 0 = +bias(optional), 1 = +bias +residual R, 2 = +bias then exact GELU
template <int OP, int K, int N>
__global__ void __launch_bounds__(256)
tgemm_kernel(const float* __restrict__ A, const float* __restrict__ B,
             const float* __restrict__ bias, const float* __restrict__ R,
             float* __restrict__ C)
{
    __shared__ float As[2][16][136];
    __shared__ float Bs[2][16][136];

    int tid  = threadIdx.x;
    int lane = tid & 31, wid = tid >> 5;
    int g = lane >> 2, tig = lane & 3;
    int warp_m = (wid & 1) * 64, warp_n = (wid >> 1) * 32;
    int row0 = blockIdx.y * 128, col0 = blockIdx.x * 128;

    int am = tid & 127, ak = (tid >> 7) * 8;
    int bn = (tid & 31) * 4, bk = tid >> 5;

    float acc[4][4][4];
    #pragma unroll
    for (int mt = 0; mt < 4; mt++)
        #pragma unroll
        for (int nt = 0; nt < 4; nt++)
            #pragma unroll
            for (int r = 0; r < 4; r++) acc[mt][nt][r] = 0.f;

    const float* Aptr = A + (size_t)(row0 + am) * K + ak;
    const float* Bptr = B + (size_t)bk * N + col0 + bn;

    float4 a0 = *(const float4*)(Aptr);
    float4 a1 = *(const float4*)(Aptr + 4);
    float4 b0 = *(const float4*)(Bptr);
    float4 b1 = *(const float4*)(Bptr + (size_t)8 * N);

    As[0][ak + 0][am] = tf32r(a0.x); As[0][ak + 1][am] = tf32r(a0.y);
    As[0][ak + 2][am] = tf32r(a0.z); As[0][ak + 3][am] = tf32r(a0.w);
    As[0][ak + 4][am] = tf32r(a1.x); As[0][ak + 5][am] = tf32r(a1.y);
    As[0][ak + 6][am] = tf32r(a1.z); As[0][ak + 7][am] = tf32r(a1.w);
    {
        float4 c0 = make_float4(tf32r(b0.x), tf32r(b0.y), tf32r(b0.z), tf32r(b0.w));
        float4 c1 = make_float4(tf32r(b1.x), tf32r(b1.y), tf32r(b1.z), tf32r(b1.w));
        *(float4*)&Bs[0][bk][bn] = c0;
        *(float4*)&Bs[0][bk + 8][bn] = c1;
    }
    __syncthreads();

    int buf = 0;
    #pragma unroll 2
    for (int k0 = 0; k0 < K; k0 += 16) {
        const bool more = (k0 + 16) < K;
        if (more) {
            a0 = *(const float4*)(Aptr + k0 + 16);
            a1 = *(const float4*)(Aptr + k0 + 20);
            b0 = *(const float4*)(Bptr + (size_t)(k0 + 16) * N);
            b1 = *(const float4*)(Bptr + (size_t)(k0 + 24) * N);
        }
        #pragma unroll
        for (int ks = 0; ks < 2; ks++) {
            int kb = ks * 8;
            uint32_t af[4][4], bfr[4][2];
            #pragma unroll
            for (int mt = 0; mt < 4; mt++) {
                int m0 = warp_m + mt * 16;
                af[mt][0] = __float_as_uint(As[buf][kb + tig    ][m0 + g    ]);
                af[mt][1] = __float_as_uint(As[buf][kb + tig    ][m0 + g + 8]);
                af[mt][2] = __float_as_uint(As[buf][kb + tig + 4][m0 + g    ]);
                af[mt][3] = __float_as_uint(As[buf][kb + tig + 4][m0 + g + 8]);
            }
            #pragma unroll
            for (int nt = 0; nt < 4; nt++) {
                int n0 = warp_n + nt * 8;
                bfr[nt][0] = __float_as_uint(Bs[buf][kb + tig    ][n0 + g]);
                bfr[nt][1] = __float_as_uint(Bs[buf][kb + tig + 4][n0 + g]);
            }
            #pragma unroll
            for (int mt = 0; mt < 4; mt++)
                #pragma unroll
                for (int nt = 0; nt < 4; nt++)
                    mma_tf32(acc[mt][nt], af[mt], bfr[nt]);
        }
        if (more) {
            int nb = buf ^ 1;
            As[nb][ak + 0][am] = tf32r(a0.x); As[nb][ak + 1][am] = tf32r(a0.y);
            As[nb][ak + 2][am] = tf32r(a0.z); As[nb][ak + 3][am] = tf32r(a0.w);
            As[nb][ak + 4][am] = tf32r(a1.x); As[nb][ak + 5][am] = tf32r(a1.y);
            As[nb][ak + 6][am] = tf32r(a1.z); As[nb][ak + 7][am] = tf32r(a1.w);
            float4 c0 = make_float4(tf32r(b0.x), tf32r(b0.y), tf32r(b0.z), tf32r(b0.w));
            float4 c1 = make_float4(tf32r(b1.x), tf32r(b1.y), tf32r(b1.z), tf32r(b1.w));
            *(float4*)&Bs[nb][bk][bn] = c0;
            *(float4*)&Bs[nb][bk + 8][bn] = c1;
            __syncthreads();
            buf = nb;
        }
    }

    #pragma unroll
    for (int mt = 0; mt < 4; mt++) {
        #pragma unroll
        for (int nt = 0; nt < 4; nt++) {
            int r = row0 + warp_m + mt * 16 + g;
            int c = col0 + warp_n + nt * 8 + 2 * tig;
            float v00 = acc[mt][nt][0], v01 = acc[mt][nt][1];
            float v10 = acc[mt][nt][2], v11 = acc[mt][nt][3];
            if (bias) {
                float2 bb = *(const float2*)&bias[c];
                v00 += bb.x; v01 += bb.y; v10 += bb.x; v11 += bb.y;
            }
            if (OP == 1) {
                float2 r0 = *(const float2*)&R[(size_t)r * N + c];
                float2 r1 = *(const float2*)&R[(size_t)(r + 8) * N + c];
                v00 += r0.x; v01 += r0.y; v10 += r1.x; v11 += r1.y;
            }
            if (OP == 2) {
                v00 = gelu_f(v00); v01 = gelu_f(v01);
                v10 = gelu_f(v10); v11 = gelu_f(v11);
            }
            float2 o0 = make_float2(v00, v01), o1 = make_float2(v10, v11);
            *(float2*)&C[(size_t)r * N + c] = o0;
            *(float2*)&C[(size_t)(r + 8) * N + c] = o1;
        }
    }
}

// ---------------- fused window attention (QK 4-row tiles, V in registers) ----------------
// grid: (64 windows, 4 heads, 32 batch); 128 threads.
__global__ void attn_kernel(const float* __restrict__ qkv,
                            const float* __restrict__ pos,
                            float* __restrict__ out, int shift)
{
    __shared__ float KT[49 * 128];     // K transposed [d][j]
    __shared__ float S[49 * 52];       // softmax probs, padded rows
    __shared__ float Qs[4][4][128];    // 4 q rows per warp
    __shared__ float poss[169];

    int tid = threadIdx.x;
    int win = blockIdx.x, head = blockIdx.y, bb = blockIdx.z;
    int win_i = win >> 3, win_j = win & 7;

    for (int idx = tid; idx < 169; idx += 128) poss[idx] = pos[idx];

    int d = tid;
    float vreg[49];
    #pragma unroll
    for (int j = 0; j < 49; j++) {
        int wi = j / 7, wj = j % 7;
        int ui = (win_i * 7 + wi + shift) % 56;
        int uj = (win_j * 7 + wj + shift) % 56;
        size_t base = (size_t)(bb * 3136 + ui * 56 + uj) * 1536 + head * 128 + d;
        KT[d * 49 + j] = qkv[base + 512];
        vreg[j]        = qkv[base + 1024];
    }
    __syncthreads();

    int w = tid >> 5, l = tid & 31;
    int j1 = (l < 17) ? (l + 32) : 0;
    const float scale = 0.08838834764831845f;  // 128^-0.5

    for (int i0 = w * 4; i0 < 49; i0 += 16) {
        __syncwarp();
        #pragma unroll
        for (int r = 0; r < 4; r++) {
            int ir = i0 + r;
            if (ir < 49) {
                int wi = ir / 7, wj = ir % 7;
                int ui = (win_i * 7 + wi + shift) % 56;
                int uj = (win_j * 7 + wj + shift) % 56;
                const float* qp =
                    &qkv[(size_t)(bb * 3136 + ui * 56 + uj) * 1536 + head * 128];
                Qs[w][r][l]      = qp[l];      Qs[w][r][l + 32] = qp[l + 32];
                Qs[w][r][l + 64] = qp[l + 64]; Qs[w][r][l + 96] = qp[l + 96];
            }
        }
        __syncwarp();

        float s0[4] = {0.f, 0.f, 0.f, 0.f}, s1[4] = {0.f, 0.f, 0.f, 0.f};
        #pragma unroll 4
        for (int dd = 0; dd < 128; dd++) {
            float k0 = KT[dd * 49 + l];
            float k1 = KT[dd * 49 + j1];
            #pragma unroll
            for (int r = 0; r < 4; r++) {
                float qv = Qs[w][r][dd];
                s0[r] += qv * k0;
                s1[r] += qv * k1;
            }
        }

        #pragma unroll
        for (int r = 0; r < 4; r++) {
            int i = i0 + r;
            if (i >= 49) break;   // warp-uniform
            int wi = i / 7, wj = i % 7;
            int jj0 = l, jj1 = l + 32;
            float v0 = s0[r] * scale + poss[(jj0 / 7 - wi + 6) * 13 + (jj0 % 7 - wj + 6)];
            float v1 = (l < 17)
                ? s1[r] * scale + poss[(jj1 / 7 - wi + 6) * 13 + (jj1 % 7 - wj + 6)]
                : -3.0e38f;
            if (shift) {
                if (win_i == 7) {
                    if ((i >= 28) != (jj0 >= 28)) v0 += NEGM;
                    if (l < 17 && ((i >= 28) != (jj1 >= 28))) v1 += NEGM;
                }
                if (win_j == 7) {
                    if ((wj >= 4) != (jj0 % 7 >= 4)) v0 += NEGM;
                    if (l < 17 && ((wj >= 4) != (jj1 % 7 >= 4))) v1 += NEGM;
                }
            }
            float m = v0; if (l < 17) m = fmaxf(m, v1);
            #pragma unroll
            for (int o = 16; o; o >>= 1) m = fmaxf(m, __shfl_xor_sync(~0u, m, o));
            float e0 = expf(v0 - m);
            float e1 = (l < 17) ? expf(v1 - m) : 0.f;
            float sm = e0 + e1;
            #pragma unroll
            for (int o = 16; o; o >>= 1) sm += __shfl_xor_sync(~0u, sm, o);
            float inv = 1.f / sm;
            S[i * 52 + jj0] = e0 * inv;
            if (l < 17) S[i * 52 + jj1] = e1 * inv;
        }
    }
    __syncthreads();

    // AV: out[i][d] = sum_j S[i][j] * vreg[j]
    #pragma unroll 1
    for (int i = 0; i < 49; i++) {
        const float* srow = &S[i * 52];
        float acc = 0.f;
        #pragma unroll
        for (int jq = 0; jq < 12; jq++) {
            float4 s4 = *(const float4*)(srow + jq * 4);
            acc += s4.x * vreg[jq * 4 + 0] + s4.y * vreg[jq * 4 + 1]
                 + s4.z * vreg[jq * 4 + 2] + s4.w * vreg[jq * 4 + 3];
        }
        acc += srow[48] * vreg[48];
        int wi = i / 7, wj = i % 7;
        int ui = (win_i * 7 + wi + shift) % 56;
        int uj = (win_j * 7 + wj + shift) % 56;
        out[(size_t)(bb * 3136 + ui * 56 + uj) * 512 + head * 128 + d] = acc;
    }
}

// ---------------- host launcher ----------------
extern "C" void kernel_launch(void* const* d_in, const int* in_sizes, int n_in,
                              void* d_out, int out_size)
{
    const float* x    = (const float*)d_in[0];
    const float* w_pe = (const float*)d_in[1];
    const float* b_pe = (const float*)d_in[2];

    float *h, *xn, *qkv, *mid;
    cudaGetSymbolAddress((void**)&h,   g_h);
    cudaGetSymbolAddress((void**)&xn,  g_xn);
    cudaGetSymbolAddress((void**)&qkv, g_qkv);
    cudaGetSymbolAddress((void**)&mid, g_mid);
    float* out = (float*)d_out;

    const float* const* pa = (const float* const*)(d_in + 3);
    const float* const* pb = (const float* const*)(d_in + 15);

    // patch embed + ln1_a fused
    patch_embed_ln_kernel<<<T_TOK, 128>>>(x, w_pe, b_pe, pa[0], pa[1], h, xn);

    for (int blk = 0; blk < 2; blk++) {
        const float* const* p = blk ? pb : pa;
        const float *wqkv = p[2], *pos = p[3], *wo = p[4], *bo = p[5],
                    *ga2 = p[6], *be2 = p[7], *w1 = p[8], *b1 = p[9],
                    *w2 = p[10], *b2 = p[11];
        int shift = blk ? DISP : 0;
        float* fin = (blk == 1) ? out : h;

        tgemm_kernel<0, DIM, QKV3><<<dim3(QKV3 / 128, T_TOK / 128), 256>>>(
            xn, wqkv, nullptr, nullptr, qkv);
        attn_kernel<<<dim3(64, HEADS, 32), 128>>>(qkv, pos, mid, shift);
        tgemm_kernel<1, INNER, DIM><<<dim3(1, T_TOK / 128), 256>>>(
            mid, wo, bo, h, h);
        ln_kernel<<<T_TOK, 128>>>(h, ga2, be2, xn);
        tgemm_kernel<2, DIM, MLPD><<<dim3(MLPD / 128, T_TOK / 128), 256>>>(
            xn, w1, b1, nullptr, mid);
        tgemm_kernel<1, MLPD, DIM><<<dim3(1, T_TOK / 128), 256>>>(
            mid, w2, b2, h, fin);
        if (blk == 0)
            ln_kernel<<<T_TOK, 128>>>(h, pb[0], pb[1], xn);
    }
}

// round 13
// speedup vs baseline: 1.6664x; 1.1397x over previous
#include <cuda_runtime.h>
#include <math.h>
#include <stdint.h>

#define T_TOK 100352   // 32*56*56 tokens
#define DIM   128
#define INNER 512
#define QKV3  1536
#define MLPD  512
#define HEADS 4
#define DISP  3
#define NEGM  (-1e9f)

// ---------------- scratch (static device globals; no allocations) ----------------
__device__ float g_h  [T_TOK * DIM];
__device__ float g_xn [T_TOK * DIM];
__device__ float g_qkv[T_TOK * QKV3];
__device__ float g_mid[T_TOK * INNER];

// ---------------- patch embed + fused LN (ln1_a) ----------------
__global__ void patch_embed_ln_kernel(const float* __restrict__ x,
                                      const float* __restrict__ w,
                                      const float* __restrict__ b,
                                      const float* __restrict__ ga,
                                      const float* __restrict__ be,
                                      float* __restrict__ out_h,
                                      float* __restrict__ out_xn)
{
    int t = blockIdx.x, n = threadIdx.x;
    __shared__ float s[48];
    __shared__ float red[4];
    int bb = t / 3136, rem = t % 3136, ph = rem / 56, pw = rem % 56;
    if (n < 48) {
        int c = n >> 4, pi = (n >> 2) & 3, pj = n & 3;
        s[n] = x[((size_t)(bb * 3 + c) * 224 + (ph * 4 + pi)) * 224 + (pw * 4 + pj)];
    }
    __syncthreads();
    float acc = b[n];
    #pragma unroll
    for (int f = 0; f < 48; f++) acc += s[f] * w[f * DIM + n];
    out_h[(size_t)t * DIM + n] = acc;

    float v = acc, sum = v;
    #pragma unroll
    for (int o = 16; o; o >>= 1) sum += __shfl_xor_sync(~0u, sum, o);
    if ((n & 31) == 0) red[n >> 5] = sum;
    __syncthreads();
    float mean = (red[0] + red[1] + red[2] + red[3]) * (1.f / 128.f);
    __syncthreads();
    float d = v - mean;
    sum = d * d;
    #pragma unroll
    for (int o = 16; o; o >>= 1) sum += __shfl_xor_sync(~0u, sum, o);
    if ((n & 31) == 0) red[n >> 5] = sum;
    __syncthreads();
    float var = (red[0] + red[1] + red[2] + red[3]) * (1.f / 128.f);
    out_xn[(size_t)t * DIM + n] = d * rsqrtf(var + 1e-5f) * ga[n] + be[n];
}

// ---------------- LayerNorm (standalone) ----------------
__global__ void ln_kernel(const float* __restrict__ x,
                          const float* __restrict__ g,
                          const float* __restrict__ b,
                          float* __restrict__ y)
{
    int t = blockIdx.x, c = threadIdx.x;
    float v = x[(size_t)t * DIM + c];
    __shared__ float red[4];
    float s = v;
    #pragma unroll
    for (int o = 16; o; o >>= 1) s += __shfl_xor_sync(~0u, s, o);
    if ((c & 31) == 0) red[c >> 5] = s;
    __syncthreads();
    float mean = (red[0] + red[1] + red[2] + red[3]) * (1.f / 128.f);
    __syncthreads();
    float d = v - mean;
    s = d * d;
    #pragma unroll
    for (int o = 16; o; o >>= 1) s += __shfl_xor_sync(~0u, s, o);
    if ((c & 31) == 0) red[c >> 5] = s;
    __syncthreads();
    float var = (red[0] + red[1] + red[2] + red[3]) * (1.f / 128.f);
    y[(size_t)t * DIM + c] = d * rsqrtf(var + 1e-5f) * g[c] + b[c];
}

// ---------------- TF32 tensor-core GEMM 128x128xBK16, 8 warps ----------------
__device__ __forceinline__ float gelu_f(float v)
{
    return 0.5f * v * (1.f + erff(v * 0.70710678118654752f));
}

__device__ __forceinline__ float tf32r(float x)
{
    uint32_t u;
    asm("cvt.rna.tf32.f32 %0, %1;" : "=r"(u) : "f"(x));
    return __uint_as_float(u);
}

__device__ __forceinline__ void mma_tf32(float c[4], const uint32_t a[4], const uint32_t b[2])
{
    asm volatile(
        "mma.sync.aligned.m16n8k8.row.col.f32.tf32.tf32.f32 "
        "{%0,%1,%2,%3}, {%4,%5,%6,%7}, {%8,%9}, {%0,%1,%2,%3};"
        : "+f"(c[0]), "+f"(c[1]), "+f"(c[2]), "+f"(c[3])
        : "r"(a[0]), "r"(a[1]), "r"(a[2]), "r"(a[3]), "r"(b[0]), "r"(b[1]));
}

// OP: 0 = +bias(optional), 1 = +bias +residual R, 2 = +bias then exact GELU
template <int OP, int K, int N>
__global__ void __launch_bounds__(256, 2)
tgemm_kernel(const float* __restrict__ A, const float* __restrict__ B,
             const float* __restrict__ bias, const float* __restrict__ R,
             float* __restrict__ C)
{
    __shared__ float As[2][16][136];
    __shared__ float Bs[2][16][136];

    int tid  = threadIdx.x;
    int lane = tid & 31, wid = tid >> 5;
    int g = lane >> 2, tig = lane & 3;
    int warp_m = (wid & 1) * 64, warp_n = (wid >> 1) * 32;
    int row0 = blockIdx.y * 128, col0 = blockIdx.x * 128;

    int am = tid & 127, ak = (tid >> 7) * 8;
    int bn = (tid & 31) * 4, bk = tid >> 5;

    float acc[4][4][4];
    #pragma unroll
    for (int mt = 0; mt < 4; mt++)
        #pragma unroll
        for (int nt = 0; nt < 4; nt++)
            #pragma unroll
            for (int r = 0; r < 4; r++) acc[mt][nt][r] = 0.f;

    const float* Aptr = A + (size_t)(row0 + am) * K + ak;
    const float* Bptr = B + (size_t)bk * N + col0 + bn;

    float4 a0 = *(const float4*)(Aptr);
    float4 a1 = *(const float4*)(Aptr + 4);
    float4 b0 = *(const float4*)(Bptr);
    float4 b1 = *(const float4*)(Bptr + (size_t)8 * N);

    As[0][ak + 0][am] = tf32r(a0.x); As[0][ak + 1][am] = tf32r(a0.y);
    As[0][ak + 2][am] = tf32r(a0.z); As[0][ak + 3][am] = tf32r(a0.w);
    As[0][ak + 4][am] = tf32r(a1.x); As[0][ak + 5][am] = tf32r(a1.y);
    As[0][ak + 6][am] = tf32r(a1.z); As[0][ak + 7][am] = tf32r(a1.w);
    {
        float4 c0 = make_float4(tf32r(b0.x), tf32r(b0.y), tf32r(b0.z), tf32r(b0.w));
        float4 c1 = make_float4(tf32r(b1.x), tf32r(b1.y), tf32r(b1.z), tf32r(b1.w));
        *(float4*)&Bs[0][bk][bn] = c0;
        *(float4*)&Bs[0][bk + 8][bn] = c1;
    }
    __syncthreads();

    int buf = 0;
    #pragma unroll 2
    for (int k0 = 0; k0 < K; k0 += 16) {
        const bool more = (k0 + 16) < K;
        if (more) {
            a0 = *(const float4*)(Aptr + k0 + 16);
            a1 = *(const float4*)(Aptr + k0 + 20);
            b0 = *(const float4*)(Bptr + (size_t)(k0 + 16) * N);
            b1 = *(const float4*)(Bptr + (size_t)(k0 + 24) * N);
        }
        #pragma unroll
        for (int ks = 0; ks < 2; ks++) {
            int kb = ks * 8;
            uint32_t af[4][4], bfr[4][2];
            #pragma unroll
            for (int mt = 0; mt < 4; mt++) {
                int m0 = warp_m + mt * 16;
                af[mt][0] = __float_as_uint(As[buf][kb + tig    ][m0 + g    ]);
                af[mt][1] = __float_as_uint(As[buf][kb + tig    ][m0 + g + 8]);
                af[mt][2] = __float_as_uint(As[buf][kb + tig + 4][m0 + g    ]);
                af[mt][3] = __float_as_uint(As[buf][kb + tig + 4][m0 + g + 8]);
            }
            #pragma unroll
            for (int nt = 0; nt < 4; nt++) {
                int n0 = warp_n + nt * 8;
                bfr[nt][0] = __float_as_uint(Bs[buf][kb + tig    ][n0 + g]);
                bfr[nt][1] = __float_as_uint(Bs[buf][kb + tig + 4][n0 + g]);
            }
            #pragma unroll
            for (int mt = 0; mt < 4; mt++)
                #pragma unroll
                for (int nt = 0; nt < 4; nt++)
                    mma_tf32(acc[mt][nt], af[mt], bfr[nt]);
        }
        if (more) {
            int nb = buf ^ 1;
            As[nb][ak + 0][am] = tf32r(a0.x); As[nb][ak + 1][am] = tf32r(a0.y);
            As[nb][ak + 2][am] = tf32r(a0.z); As[nb][ak + 3][am] = tf32r(a0.w);
            As[nb][ak + 4][am] = tf32r(a1.x); As[nb][ak + 5][am] = tf32r(a1.y);
            As[nb][ak + 6][am] = tf32r(a1.z); As[nb][ak + 7][am] = tf32r(a1.w);
            float4 c0 = make_float4(tf32r(b0.x), tf32r(b0.y), tf32r(b0.z), tf32r(b0.w));
            float4 c1 = make_float4(tf32r(b1.x), tf32r(b1.y), tf32r(b1.z), tf32r(b1.w));
            *(float4*)&Bs[nb][bk][bn] = c0;
            *(float4*)&Bs[nb][bk + 8][bn] = c1;
            __syncthreads();
            buf = nb;
        }
    }

    #pragma unroll
    for (int mt = 0; mt < 4; mt++) {
        #pragma unroll
        for (int nt = 0; nt < 4; nt++) {
            int r = row0 + warp_m + mt * 16 + g;
            int c = col0 + warp_n + nt * 8 + 2 * tig;
            float v00 = acc[mt][nt][0], v01 = acc[mt][nt][1];
            float v10 = acc[mt][nt][2], v11 = acc[mt][nt][3];
            if (bias) {
                float2 bb = *(const float2*)&bias[c];
                v00 += bb.x; v01 += bb.y; v10 += bb.x; v11 += bb.y;
            }
            if (OP == 1) {
                float2 r0 = *(const float2*)&R[(size_t)r * N + c];
                float2 r1 = *(const float2*)&R[(size_t)(r + 8) * N + c];
                v00 += r0.x; v01 += r0.y; v10 += r1.x; v11 += r1.y;
            }
            if (OP == 2) {
                v00 = gelu_f(v00); v01 = gelu_f(v01);
                v10 = gelu_f(v10); v11 = gelu_f(v11);
            }
            float2 o0 = make_float2(v00, v01), o1 = make_float2(v10, v11);
            *(float2*)&C[(size_t)r * N + c] = o0;
            *(float2*)&C[(size_t)(r + 8) * N + c] = o1;
        }
    }
}

// ---------------- fused window attention (QK 4-row tiles, V in registers) ----------------
// grid: (64 windows, 4 heads, 32 batch); 128 threads.
__global__ void attn_kernel(const float* __restrict__ qkv,
                            const float* __restrict__ pos,
                            float* __restrict__ out, int shift)
{
    __shared__ float KT[49 * 128];     // K transposed [d][j]
    __shared__ float S[49 * 52];       // softmax probs, padded rows
    __shared__ float Qs[4][4][128];    // 4 q rows per warp
    __shared__ float poss[169];

    int tid = threadIdx.x;
    int win = blockIdx.x, head = blockIdx.y, bb = blockIdx.z;
    int win_i = win >> 3, win_j = win & 7;

    for (int idx = tid; idx < 169; idx += 128) poss[idx] = pos[idx];

    int d = tid;
    float vreg[49];
    #pragma unroll
    for (int j = 0; j < 49; j++) {
        int wi = j / 7, wj = j % 7;
        int ui = (win_i * 7 + wi + shift) % 56;
        int uj = (win_j * 7 + wj + shift) % 56;
        size_t base = (size_t)(bb * 3136 + ui * 56 + uj) * 1536 + head * 128 + d;
        KT[d * 49 + j] = qkv[base + 512];
        vreg[j]        = qkv[base + 1024];
    }
    __syncthreads();

    int w = tid >> 5, l = tid & 31;
    int j1 = (l < 17) ? (l + 32) : 0;
    const float scale = 0.08838834764831845f;  // 128^-0.5

    for (int i0 = w * 4; i0 < 49; i0 += 16) {
        __syncwarp();
        #pragma unroll
        for (int r = 0; r < 4; r++) {
            int ir = i0 + r;
            if (ir < 49) {
                int wi = ir / 7, wj = ir % 7;
                int ui = (win_i * 7 + wi + shift) % 56;
                int uj = (win_j * 7 + wj + shift) % 56;
                const float* qp =
                    &qkv[(size_t)(bb * 3136 + ui * 56 + uj) * 1536 + head * 128];
                Qs[w][r][l]      = qp[l];      Qs[w][r][l + 32] = qp[l + 32];
                Qs[w][r][l + 64] = qp[l + 64]; Qs[w][r][l + 96] = qp[l + 96];
            }
        }
        __syncwarp();

        float s0[4] = {0.f, 0.f, 0.f, 0.f}, s1[4] = {0.f, 0.f, 0.f, 0.f};
        #pragma unroll 4
        for (int dd = 0; dd < 128; dd++) {
            float k0 = KT[dd * 49 + l];
            float k1 = KT[dd * 49 + j1];
            #pragma unroll
            for (int r = 0; r < 4; r++) {
                float qv = Qs[w][r][dd];
                s0[r] += qv * k0;
                s1[r] += qv * k1;
            }
        }

        #pragma unroll
        for (int r = 0; r < 4; r++) {
            int i = i0 + r;
            if (i >= 49) break;   // warp-uniform
            int wi = i / 7, wj = i % 7;
            int jj0 = l, jj1 = l + 32;
            float v0 = s0[r] * scale + poss[(jj0 / 7 - wi + 6) * 13 + (jj0 % 7 - wj + 6)];
            float v1 = (l < 17)
                ? s1[r] * scale + poss[(jj1 / 7 - wi + 6) * 13 + (jj1 % 7 - wj + 6)]
                : -3.0e38f;
            if (shift) {
                if (win_i == 7) {
                    if ((i >= 28) != (jj0 >= 28)) v0 += NEGM;
                    if (l < 17 && ((i >= 28) != (jj1 >= 28))) v1 += NEGM;
                }
                if (win_j == 7) {
                    if ((wj >= 4) != (jj0 % 7 >= 4)) v0 += NEGM;
                    if (l < 17 && ((wj >= 4) != (jj1 % 7 >= 4))) v1 += NEGM;
                }
            }
            float m = v0; if (l < 17) m = fmaxf(m, v1);
            #pragma unroll
            for (int o = 16; o; o >>= 1) m = fmaxf(m, __shfl_xor_sync(~0u, m, o));
            float e0 = expf(v0 - m);
            float e1 = (l < 17) ? expf(v1 - m) : 0.f;
            float sm = e0 + e1;
            #pragma unroll
            for (int o = 16; o; o >>= 1) sm += __shfl_xor_sync(~0u, sm, o);
            float inv = 1.f / sm;
            S[i * 52 + jj0] = e0 * inv;
            if (l < 17) S[i * 52 + jj1] = e1 * inv;
        }
    }
    __syncthreads();

    // AV: out[i][d] = sum_j S[i][j] * vreg[j]
    #pragma unroll 1
    for (int i = 0; i < 49; i++) {
        const float* srow = &S[i * 52];
        float acc = 0.f;
        #pragma unroll
        for (int jq = 0; jq < 12; jq++) {
            float4 s4 = *(const float4*)(srow + jq * 4);
            acc += s4.x * vreg[jq * 4 + 0] + s4.y * vreg[jq * 4 + 1]
                 + s4.z * vreg[jq * 4 + 2] + s4.w * vreg[jq * 4 + 3];
        }
        acc += srow[48] * vreg[48];
        int wi = i / 7, wj = i % 7;
        int ui = (win_i * 7 + wi + shift) % 56;
        int uj = (win_j * 7 + wj + shift) % 56;
        out[(size_t)(bb * 3136 + ui * 56 + uj) * 512 + head * 128 + d] = acc;
    }
}

// ---------------- host launcher ----------------
extern "C" void kernel_launch(void* const* d_in, const int* in_sizes, int n_in,
                              void* d_out, int out_size)
{
    const float* x    = (const float*)d_in[0];
    const float* w_pe = (const float*)d_in[1];
    const float* b_pe = (const float*)d_in[2];

    float *h, *xn, *qkv, *mid;
    cudaGetSymbolAddress((void**)&h,   g_h);
    cudaGetSymbolAddress((void**)&xn,  g_xn);
    cudaGetSymbolAddress((void**)&qkv, g_qkv);
    cudaGetSymbolAddress((void**)&mid, g_mid);
    float* out = (float*)d_out;

    const float* const* pa = (const float* const*)(d_in + 3);
    const float* const* pb = (const float* const*)(d_in + 15);

    // patch embed + ln1_a fused
    patch_embed_ln_kernel<<<T_TOK, 128>>>(x, w_pe, b_pe, pa[0], pa[1], h, xn);

    for (int blk = 0; blk < 2; blk++) {
        const float* const* p = blk ? pb : pa;
        const float *wqkv = p[2], *pos = p[3], *wo = p[4], *bo = p[5],
                    *ga2 = p[6], *be2 = p[7], *w1 = p[8], *b1 = p[9],
                    *w2 = p[10], *b2 = p[11];
        int shift = blk ? DISP : 0;
        float* fin = (blk == 1) ? out : h;

        tgemm_kernel<0, DIM, QKV3><<<dim3(QKV3 / 128, T_TOK / 128), 256>>>(
            xn, wqkv, nullptr, nullptr, qkv);
        attn_kernel<<<dim3(64, HEADS, 32), 128>>>(qkv, pos, mid, shift);
        tgemm_kernel<1, INNER, DIM><<<dim3(1, T_TOK / 128), 256>>>(
            mid, wo, bo, h, h);
        ln_kernel<<<T_TOK, 128>>>(h, ga2, be2, xn);
        tgemm_kernel<2, DIM, MLPD><<<dim3(MLPD / 128, T_TOK / 128), 256>>>(
            xn, w1, b1, nullptr, mid);
        tgemm_kernel<1, MLPD, DIM><<<dim3(1, T_TOK / 128), 256>>>(
            mid, w2, b2, h, fin);
        if (blk == 0)
            ln_kernel<<<T_TOK, 128>>>(h, pb[0], pb[1], xn);
    }
}

// round 14
// speedup vs baseline: 1.9289x; 1.1575x over previous
#include <cuda_runtime.h>
#include <math.h>
#include <stdint.h>

#define T_TOK 100352   // 32*56*56 tokens
#define DIM   128
#define INNER 512
#define QKV3  1536
#define MLPD  512
#define HEADS 4
#define DISP  3
#define NEGM  (-1e9f)

// ---------------- scratch (static device globals; no allocations) ----------------
__device__ float g_h  [T_TOK * DIM];
__device__ float g_xn [T_TOK * DIM];
__device__ float g_qkv[T_TOK * QKV3];
__device__ float g_mid[T_TOK * INNER];

// ---------------- patch embed + fused LN (ln1_a) ----------------
__global__ void patch_embed_ln_kernel(const float* __restrict__ x,
                                      const float* __restrict__ w,
                                      const float* __restrict__ b,
                                      const float* __restrict__ ga,
                                      const float* __restrict__ be,
                                      float* __restrict__ out_h,
                                      float* __restrict__ out_xn)
{
    int t = blockIdx.x, n = threadIdx.x;
    __shared__ float s[48];
    __shared__ float red[4];
    int bb = t / 3136, rem = t % 3136, ph = rem / 56, pw = rem % 56;
    if (n < 48) {
        int c = n >> 4, pi = (n >> 2) & 3, pj = n & 3;
        s[n] = x[((size_t)(bb * 3 + c) * 224 + (ph * 4 + pi)) * 224 + (pw * 4 + pj)];
    }
    __syncthreads();
    float acc = b[n];
    #pragma unroll
    for (int f = 0; f < 48; f++) acc += s[f] * w[f * DIM + n];
    out_h[(size_t)t * DIM + n] = acc;

    float v = acc, sum = v;
    #pragma unroll
    for (int o = 16; o; o >>= 1) sum += __shfl_xor_sync(~0u, sum, o);
    if ((n & 31) == 0) red[n >> 5] = sum;
    __syncthreads();
    float mean = (red[0] + red[1] + red[2] + red[3]) * (1.f / 128.f);
    __syncthreads();
    float d = v - mean;
    sum = d * d;
    #pragma unroll
    for (int o = 16; o; o >>= 1) sum += __shfl_xor_sync(~0u, sum, o);
    if ((n & 31) == 0) red[n >> 5] = sum;
    __syncthreads();
    float var = (red[0] + red[1] + red[2] + red[3]) * (1.f / 128.f);
    out_xn[(size_t)t * DIM + n] = d * rsqrtf(var + 1e-5f) * ga[n] + be[n];
}

// ---------------- LayerNorm (standalone) ----------------
__global__ void ln_kernel(const float* __restrict__ x,
                          const float* __restrict__ g,
                          const float* __restrict__ b,
                          float* __restrict__ y)
{
    int t = blockIdx.x, c = threadIdx.x;
    float v = x[(size_t)t * DIM + c];
    __shared__ float red[4];
    float s = v;
    #pragma unroll
    for (int o = 16; o; o >>= 1) s += __shfl_xor_sync(~0u, s, o);
    if ((c & 31) == 0) red[c >> 5] = s;
    __syncthreads();
    float mean = (red[0] + red[1] + red[2] + red[3]) * (1.f / 128.f);
    __syncthreads();
    float d = v - mean;
    s = d * d;
    #pragma unroll
    for (int o = 16; o; o >>= 1) s += __shfl_xor_sync(~0u, s, o);
    if ((c & 31) == 0) red[c >> 5] = s;
    __syncthreads();
    float var = (red[0] + red[1] + red[2] + red[3]) * (1.f / 128.f);
    y[(size_t)t * DIM + c] = d * rsqrtf(var + 1e-5f) * g[c] + b[c];
}

// ---------------- TF32 tensor-core GEMM, cp.async 3-stage pipeline ----------------
__device__ __forceinline__ float gelu_f(float v)
{
    return 0.5f * v * (1.f + erff(v * 0.70710678118654752f));
}

__device__ __forceinline__ void mma_tf32(float c[4], const uint32_t a[4], const uint32_t b[2])
{
    asm volatile(
        "mma.sync.aligned.m16n8k8.row.col.f32.tf32.tf32.f32 "
        "{%0,%1,%2,%3}, {%4,%5,%6,%7}, {%8,%9}, {%0,%1,%2,%3};"
        : "+f"(c[0]), "+f"(c[1]), "+f"(c[2]), "+f"(c[3])
        : "r"(a[0]), "r"(a[1]), "r"(a[2]), "r"(a[3]), "r"(b[0]), "r"(b[1]));
}

__device__ __forceinline__ void cp16(uint32_t dst, const float* src)
{
    asm volatile("cp.async.cg.shared.global [%0], [%1], 16;"
                 :: "r"(dst), "l"(src) : "memory");
}

// smem layout (floats): As [3][128][20] then Bs [3][16][136]
#define A_STAGE 2560      // 128*20
#define B_STAGE 2176      // 16*136
#define B_OFF   7680      // 3*A_STAGE
#define GEMM_SMEM_BYTES ((3 * A_STAGE + 3 * B_STAGE) * 4)   // 56832

// OP: 0 = +bias(optional), 1 = +bias +residual R, 2 = +bias then exact GELU
template <int OP, int K, int N>
__global__ void __launch_bounds__(256, 2)
tgemm_kernel(const float* __restrict__ A, const float* __restrict__ B,
             const float* __restrict__ bias, const float* __restrict__ R,
             float* __restrict__ C)
{
    extern __shared__ float dsm[];
    uint32_t sbase = (uint32_t)__cvta_generic_to_shared(dsm);

    const int tid  = threadIdx.x;
    const int lane = tid & 31, wid = tid >> 5;
    const int g = lane >> 2, tig = lane & 3;
    const int warp_m = (wid & 1) * 64, warp_n = (wid >> 1) * 32;
    const int row0 = blockIdx.y * 128, col0 = blockIdx.x * 128;

    const int am = tid & 127, akh = (tid >> 7) * 8;  // A loader: row am, k-half
    const int bk = tid >> 5,  bn = (tid & 31) * 4;   // B loader: rows bk,bk+8

    float acc[4][4][4];
    #pragma unroll
    for (int mt = 0; mt < 4; mt++)
        #pragma unroll
        for (int nt = 0; nt < 4; nt++)
            #pragma unroll
            for (int r = 0; r < 4; r++) acc[mt][nt][r] = 0.f;

    const float* Ag = A + (size_t)(row0 + am) * K + akh;
    const float* Bg = B + (size_t)bk * N + col0 + bn;

    const uint32_t a_dst0 = sbase + (am * 20 + akh) * 4;
    const uint32_t b_dst0 = sbase + (B_OFF + bk * 136 + bn) * 4;
    const uint32_t b_dst1 = sbase + (B_OFF + (bk + 8) * 136 + bn) * 4;

    // prologue: stages 0,1
    #pragma unroll
    for (int s = 0; s < 2; s++) {
        int k0 = s * 16;
        cp16(a_dst0 + s * A_STAGE * 4, Ag + k0);
        cp16(a_dst0 + s * A_STAGE * 4 + 16, Ag + k0 + 4);
        cp16(b_dst0 + s * B_STAGE * 4, Bg + (size_t)k0 * N);
        cp16(b_dst1 + s * B_STAGE * 4, Bg + (size_t)(k0 + 8) * N);
        asm volatile("cp.async.commit_group;" ::: "memory");
    }

    const int NSTEP = K / 16;
    for (int step = 0; step < NSTEP; step++) {
        asm volatile("cp.async.wait_group 1;" ::: "memory");
        __syncthreads();
        if (step + 2 < NSTEP) {
            int s = (step + 2) % 3, k0 = (step + 2) * 16;
            cp16(a_dst0 + s * A_STAGE * 4, Ag + k0);
            cp16(a_dst0 + s * A_STAGE * 4 + 16, Ag + k0 + 4);
            cp16(b_dst0 + s * B_STAGE * 4, Bg + (size_t)k0 * N);
            cp16(b_dst1 + s * B_STAGE * 4, Bg + (size_t)(k0 + 8) * N);
        }
        asm volatile("cp.async.commit_group;" ::: "memory");

        int buf = step % 3;
        const float* Ab = dsm + buf * A_STAGE;
        const float* Bb = dsm + B_OFF + buf * B_STAGE;
        #pragma unroll
        for (int ks = 0; ks < 2; ks++) {
            int kb = ks * 8;
            uint32_t af[4][4], bfr[4][2];
            #pragma unroll
            for (int mt = 0; mt < 4; mt++) {
                int m0 = warp_m + mt * 16;
                af[mt][0] = __float_as_uint(Ab[(m0 + g    ) * 20 + kb + tig    ]);
                af[mt][1] = __float_as_uint(Ab[(m0 + g + 8) * 20 + kb + tig    ]);
                af[mt][2] = __float_as_uint(Ab[(m0 + g    ) * 20 + kb + tig + 4]);
                af[mt][3] = __float_as_uint(Ab[(m0 + g + 8) * 20 + kb + tig + 4]);
            }
            #pragma unroll
            for (int nt = 0; nt < 4; nt++) {
                int n0 = warp_n + nt * 8;
                bfr[nt][0] = __float_as_uint(Bb[(kb + tig    ) * 136 + n0 + g]);
                bfr[nt][1] = __float_as_uint(Bb[(kb + tig + 4) * 136 + n0 + g]);
            }
            #pragma unroll
            for (int mt = 0; mt < 4; mt++)
                #pragma unroll
                for (int nt = 0; nt < 4; nt++)
                    mma_tf32(acc[mt][nt], af[mt], bfr[nt]);
        }
    }

    #pragma unroll
    for (int mt = 0; mt < 4; mt++) {
        #pragma unroll
        for (int nt = 0; nt < 4; nt++) {
            int r = row0 + warp_m + mt * 16 + g;
            int c = col0 + warp_n + nt * 8 + 2 * tig;
            float v00 = acc[mt][nt][0], v01 = acc[mt][nt][1];
            float v10 = acc[mt][nt][2], v11 = acc[mt][nt][3];
            if (bias) {
                float2 bb = *(const float2*)&bias[c];
                v00 += bb.x; v01 += bb.y; v10 += bb.x; v11 += bb.y;
            }
            if (OP == 1) {
                float2 r0 = *(const float2*)&R[(size_t)r * N + c];
                float2 r1 = *(const float2*)&R[(size_t)(r + 8) * N + c];
                v00 += r0.x; v01 += r0.y; v10 += r1.x; v11 += r1.y;
            }
            if (OP == 2) {
                v00 = gelu_f(v00); v01 = gelu_f(v01);
                v10 = gelu_f(v10); v11 = gelu_f(v11);
            }
            float2 o0 = make_float2(v00, v01), o1 = make_float2(v10, v11);
            *(float2*)&C[(size_t)r * N + c] = o0;
            *(float2*)&C[(size_t)(r + 8) * N + c] = o1;
        }
    }
}

// ---------------- fused window attention (QK 4-row tiles, V in registers) ----------------
// grid: (64 windows, 4 heads, 32 batch); 128 threads.
__global__ void attn_kernel(const float* __restrict__ qkv,
                            const float* __restrict__ pos,
                            float* __restrict__ out, int shift)
{
    __shared__ float KT[49 * 128];     // K transposed [d][j]
    __shared__ float S[49 * 52];       // softmax probs, padded rows
    __shared__ float Qs[4][4][128];    // 4 q rows per warp
    __shared__ float poss[169];

    int tid = threadIdx.x;
    int win = blockIdx.x, head = blockIdx.y, bb = blockIdx.z;
    int win_i = win >> 3, win_j = win & 7;

    for (int idx = tid; idx < 169; idx += 128) poss[idx] = pos[idx];

    int d = tid;
    float vreg[49];
    #pragma unroll
    for (int j = 0; j < 49; j++) {
        int wi = j / 7, wj = j % 7;
        int ui = (win_i * 7 + wi + shift) % 56;
        int uj = (win_j * 7 + wj + shift) % 56;
        size_t base = (size_t)(bb * 3136 + ui * 56 + uj) * 1536 + head * 128 + d;
        KT[d * 49 + j] = qkv[base + 512];
        vreg[j]        = qkv[base + 1024];
    }
    __syncthreads();

    int w = tid >> 5, l = tid & 31;
    int j1 = (l < 17) ? (l + 32) : 0;
    const float scale = 0.08838834764831845f;  // 128^-0.5

    for (int i0 = w * 4; i0 < 49; i0 += 16) {
        __syncwarp();
        #pragma unroll
        for (int r = 0; r < 4; r++) {
            int ir = i0 + r;
            if (ir < 49) {
                int wi = ir / 7, wj = ir % 7;
                int ui = (win_i * 7 + wi + shift) % 56;
                int uj = (win_j * 7 + wj + shift) % 56;
                const float* qp =
                    &qkv[(size_t)(bb * 3136 + ui * 56 + uj) * 1536 + head * 128];
                Qs[w][r][l]      = qp[l];      Qs[w][r][l + 32] = qp[l + 32];
                Qs[w][r][l + 64] = qp[l + 64]; Qs[w][r][l + 96] = qp[l + 96];
            }
        }
        __syncwarp();

        float s0[4] = {0.f, 0.f, 0.f, 0.f}, s1[4] = {0.f, 0.f, 0.f, 0.f};
        #pragma unroll 4
        for (int dd = 0; dd < 128; dd++) {
            float k0 = KT[dd * 49 + l];
            float k1 = KT[dd * 49 + j1];
            #pragma unroll
            for (int r = 0; r < 4; r++) {
                float qv = Qs[w][r][dd];
                s0[r] += qv * k0;
                s1[r] += qv * k1;
            }
        }

        #pragma unroll
        for (int r = 0; r < 4; r++) {
            int i = i0 + r;
            if (i >= 49) break;   // warp-uniform
            int wi = i / 7, wj = i % 7;
            int jj0 = l, jj1 = l + 32;
            float v0 = s0[r] * scale + poss[(jj0 / 7 - wi + 6) * 13 + (jj0 % 7 - wj + 6)];
            float v1 = (l < 17)
                ? s1[r] * scale + poss[(jj1 / 7 - wi + 6) * 13 + (jj1 % 7 - wj + 6)]
                : -3.0e38f;
            if (shift) {
                if (win_i == 7) {
                    if ((i >= 28) != (jj0 >= 28)) v0 += NEGM;
                    if (l < 17 && ((i >= 28) != (jj1 >= 28))) v1 += NEGM;
                }
                if (win_j == 7) {
                    if ((wj >= 4) != (jj0 % 7 >= 4)) v0 += NEGM;
                    if (l < 17 && ((wj >= 4) != (jj1 % 7 >= 4))) v1 += NEGM;
                }
            }
            float m = v0; if (l < 17) m = fmaxf(m, v1);
            #pragma unroll
            for (int o = 16; o; o >>= 1) m = fmaxf(m, __shfl_xor_sync(~0u, m, o));
            float e0 = expf(v0 - m);
            float e1 = (l < 17) ? expf(v1 - m) : 0.f;
            float sm = e0 + e1;
            #pragma unroll
            for (int o = 16; o; o >>= 1) sm += __shfl_xor_sync(~0u, sm, o);
            float inv = 1.f / sm;
            S[i * 52 + jj0] = e0 * inv;
            if (l < 17) S[i * 52 + jj1] = e1 * inv;
        }
    }
    __syncthreads();

    // AV: out[i][d] = sum_j S[i][j] * vreg[j]
    #pragma unroll 1
    for (int i = 0; i < 49; i++) {
        const float* srow = &S[i * 52];
        float acc = 0.f;
        #pragma unroll
        for (int jq = 0; jq < 12; jq++) {
            float4 s4 = *(const float4*)(srow + jq * 4);
            acc += s4.x * vreg[jq * 4 + 0] + s4.y * vreg[jq * 4 + 1]
                 + s4.z * vreg[jq * 4 + 2] + s4.w * vreg[jq * 4 + 3];
        }
        acc += srow[48] * vreg[48];
        int wi = i / 7, wj = i % 7;
        int ui = (win_i * 7 + wi + shift) % 56;
        int uj = (win_j * 7 + wj + shift) % 56;
        out[(size_t)(bb * 3136 + ui * 56 + uj) * 512 + head * 128 + d] = acc;
    }
}

// ---------------- host launcher ----------------
extern "C" void kernel_launch(void* const* d_in, const int* in_sizes, int n_in,
                              void* d_out, int out_size)
{
    const float* x    = (const float*)d_in[0];
    const float* w_pe = (const float*)d_in[1];
    const float* b_pe = (const float*)d_in[2];

    float *h, *xn, *qkv, *mid;
    cudaGetSymbolAddress((void**)&h,   g_h);
    cudaGetSymbolAddress((void**)&xn,  g_xn);
    cudaGetSymbolAddress((void**)&qkv, g_qkv);
    cudaGetSymbolAddress((void**)&mid, g_mid);
    float* out = (float*)d_out;

    // opt-in dynamic smem (host-side attr set; idempotent, not a stream op)
    static bool attr_done = false;
    if (!attr_done) {
        cudaFuncSetAttribute(tgemm_kernel<0, DIM, QKV3>,
                             cudaFuncAttributeMaxDynamicSharedMemorySize, GEMM_SMEM_BYTES);
        cudaFuncSetAttribute(tgemm_kernel<1, INNER, DIM>,
                             cudaFuncAttributeMaxDynamicSharedMemorySize, GEMM_SMEM_BYTES);
        cudaFuncSetAttribute(tgemm_kernel<2, DIM, MLPD>,
                             cudaFuncAttributeMaxDynamicSharedMemorySize, GEMM_SMEM_BYTES);
        cudaFuncSetAttribute(tgemm_kernel<1, MLPD, DIM>,
                             cudaFuncAttributeMaxDynamicSharedMemorySize, GEMM_SMEM_BYTES);
        attr_done = true;
    }

    const float* const* pa = (const float* const*)(d_in + 3);
    const float* const* pb = (const float* const*)(d_in + 15);

    // patch embed + ln1_a fused
    patch_embed_ln_kernel<<<T_TOK, 128>>>(x, w_pe, b_pe, pa[0], pa[1], h, xn);

    for (int blk = 0; blk < 2; blk++) {
        const float* const* p = blk ? pb : pa;
        const float *wqkv = p[2], *pos = p[3], *wo = p[4], *bo = p[5],
                    *ga2 = p[6], *be2 = p[7], *w1 = p[8], *b1 = p[9],
                    *w2 = p[10], *b2 = p[11];
        int shift = blk ? DISP : 0;
        float* fin = (blk == 1) ? out : h;

        tgemm_kernel<0, DIM, QKV3><<<dim3(QKV3 / 128, T_TOK / 128), 256, GEMM_SMEM_BYTES>>>(
            xn, wqkv, nullptr, nullptr, qkv);
        attn_kernel<<<dim3(64, HEADS, 32), 128>>>(qkv, pos, mid, shift);
        tgemm_kernel<1, INNER, DIM><<<dim3(1, T_TOK / 128), 256, GEMM_SMEM_BYTES>>>(
            mid, wo, bo, h, h);
        ln_kernel<<<T_TOK, 128>>>(h, ga2, be2, xn);
        tgemm_kernel<2, DIM, MLPD><<<dim3(MLPD / 128, T_TOK / 128), 256, GEMM_SMEM_BYTES>>>(
            xn, w1, b1, nullptr, mid);
        tgemm_kernel<1, MLPD, DIM><<<dim3(1, T_TOK / 128), 256, GEMM_SMEM_BYTES>>>(
            mid, w2, b2, h, fin);
        if (blk == 0)
            ln_kernel<<<T_TOK, 128>>>(h, pb[0], pb[1], xn);
    }
}